// round 3
// baseline (speedup 1.0000x reference)
#include <cuda_runtime.h>

#define NN 4096
#define NF 4096
#define HH 4
#define OO 8
#define C32 32
#define ALPHA 0.2f
#define KSPLIT 8
#define JSPLIT 8

typedef unsigned long long ull;

// ---------------- device scratch ----------------
__device__ float  g_Wc[NF * C32];               // repacked W: [k][h*8+o]
__device__ float  g_Whp[KSPLIT][NN * C32];      // GEMM k-split partials
__device__ float  g_Wh[NN * C32];               // Wh: [node][h*8+o]
__device__ float  g_ssrc[HH][NN];
__device__ float  g_sdst[HH][NN];
__device__ float  g_pmax[HH][16];               // per-block partial max of s_dst
__device__ float  g_part[JSPLIT][HH][NN][OO];   // attention numerator partials
__device__ float  g_pden[JSPLIT][HH][NN];       // denominator partials
__device__ float  g_outpart[16][OO];            // final linear partials

__device__ __forceinline__ ull fma2(ull a, ull b, ull c) {
    ull d;
    asm("fma.rn.f32x2 %0, %1, %2, %3;" : "=l"(d) : "l"(a), "l"(b), "l"(c));
    return d;
}
__device__ __forceinline__ ull pack2(float v) {
    ull d; unsigned u = __float_as_uint(v);
    asm("mov.b64 %0, {%1, %1};" : "=l"(d) : "r"(u));
    return d;
}

// ---------------- K0: repack W [H][F][O] -> [F][H*O] ----------------
__global__ void k0_repack(const float* __restrict__ W) {
    int idx = blockIdx.x * 256 + threadIdx.x;
    if (idx < NF * C32) {
        int k = idx >> 5, c = idx & 31;
        int h = c >> 3, o = c & 7;
        g_Wc[idx] = W[(h * NF + k) * OO + o];
    }
}

// ---------------- K1: Wh = x @ Wc  (4 rows x 8 cols per thread) ----------------
// grid (32 rowblocks of 128 rows, KSPLIT), 128 threads
__global__ void __launch_bounds__(128) k1_gemm(const float* __restrict__ x) {
    __shared__ __align__(16) float xs[128 * 68];   // 34.8 KB row-major
    __shared__ __align__(16) float ws[64 * 32];    // 8 KB
    const int rb = blockIdx.x, ks = blockIdx.y;
    const int i0 = rb * 128, k0 = ks * 512;
    const int t = threadIdx.x;
    const int rg = t >> 2;           // 0..31, rows rg, rg+32, rg+64, rg+96
    const int cg = t & 3;            // 0..3, cols cg*8 .. cg*8+7

    ull acc[16];
    #pragma unroll
    for (int q = 0; q < 16; q++) acc[q] = 0;

    for (int kb = 0; kb < 512; kb += 64) {
        __syncthreads();
        // xs: 128 rows x 64 k = 2048 float4
        #pragma unroll
        for (int it = 0; it < 16; it++) {
            int idx = t + it * 128;
            int rr = idx >> 4, c4 = (idx & 15) << 2;
            *(float4*)&xs[rr * 68 + c4] =
                *(const float4*)&x[(size_t)(i0 + rr) * NF + k0 + kb + c4];
        }
        // ws: 64 k x 32 cols = 512 float4
        #pragma unroll
        for (int it = 0; it < 4; it++) {
            int idx = t + it * 128;
            int rr = idx >> 3, c4 = (idx & 7) << 2;
            *(float4*)&ws[rr * 32 + c4] = *(const float4*)&g_Wc[(k0 + kb + rr) * 32 + c4];
        }
        __syncthreads();
        #pragma unroll 4
        for (int kk = 0; kk < 64; kk++) {
            ulonglong2 wA = *(const ulonglong2*)&ws[kk * 32 + cg * 8];
            ulonglong2 wB = *(const ulonglong2*)&ws[kk * 32 + cg * 8 + 4];
            #pragma unroll
            for (int m = 0; m < 4; m++) {
                ull xx = pack2(xs[(rg + 32 * m) * 68 + kk]);
                acc[m * 4 + 0] = fma2(xx, wA.x, acc[m * 4 + 0]);
                acc[m * 4 + 1] = fma2(xx, wA.y, acc[m * 4 + 1]);
                acc[m * 4 + 2] = fma2(xx, wB.x, acc[m * 4 + 2]);
                acc[m * 4 + 3] = fma2(xx, wB.y, acc[m * 4 + 3]);
            }
        }
    }
    #pragma unroll
    for (int m = 0; m < 4; m++) {
        ull* dst = (ull*)&g_Whp[ks][(size_t)(i0 + rg + 32 * m) * 32 + cg * 8];
        dst[0] = acc[m * 4 + 0]; dst[1] = acc[m * 4 + 1];
        dst[2] = acc[m * 4 + 2]; dst[3] = acc[m * 4 + 3];
    }
}

// ---------------- K2a: reduce k-split partials, scores + partial maxes ----------------
__global__ void __launch_bounds__(256) k2a_scores(const float* __restrict__ a) {
    __shared__ float sa[64];
    __shared__ float mred[HH][8];
    int t = threadIdx.x;
    if (t < 64) sa[t] = a[t];
    __syncthreads();
    int i = blockIdx.x * 256 + t;
    const int lane = t & 31, warp = t >> 5;

    float wh[32];
    #pragma unroll
    for (int c4 = 0; c4 < 8; c4++) {
        float4 s = make_float4(0.f, 0.f, 0.f, 0.f);
        #pragma unroll
        for (int ks = 0; ks < KSPLIT; ks++) {
            float4 v = *(const float4*)&g_Whp[ks][i * 32 + c4 * 4];
            s.x += v.x; s.y += v.y; s.z += v.z; s.w += v.w;
        }
        *(float4*)&g_Wh[i * 32 + c4 * 4] = s;
        wh[c4 * 4 + 0] = s.x; wh[c4 * 4 + 1] = s.y;
        wh[c4 * 4 + 2] = s.z; wh[c4 * 4 + 3] = s.w;
    }
    float sdv[HH];
    #pragma unroll
    for (int h = 0; h < HH; h++) {
        float ss = 0.f, sd = 0.f;
        #pragma unroll
        for (int o = 0; o < OO; o++) {
            ss += wh[h * 8 + o] * sa[h * 16 + o];
            sd += wh[h * 8 + o] * sa[h * 16 + 8 + o];
        }
        g_ssrc[h][i] = ss;
        g_sdst[h][i] = sd;
        sdv[h] = sd;
    }
    // per-head block max of s_dst
    #pragma unroll
    for (int h = 0; h < HH; h++) {
        float m = sdv[h];
        #pragma unroll
        for (int o = 16; o; o >>= 1) m = fmaxf(m, __shfl_xor_sync(0xffffffffu, m, o));
        if (lane == 0) mred[h][warp] = m;
    }
    __syncthreads();
    if (t < HH) {
        float m = -1e30f;
        #pragma unroll
        for (int w = 0; w < 8; w++) m = fmaxf(m, mred[t][w]);
        g_pmax[t][blockIdx.x] = m;
    }
}

// ---------------- K3: attention aggregation (hot kernel, factors fused) ----------------
// grid (64 rowblocks, 8 j-splits), 256 threads = 4 heads x 64 rows
__global__ void __launch_bounds__(256) k3_attn(const int* __restrict__ adj) {
    __shared__ __align__(16) float Whs[128 * 32];   // 16 KB
    __shared__ float2 pqs[HH][128];                 // 4 KB (p, q) per (head, j)
    __shared__ uint4  maskJ4[64];                   // 1 KB
    __shared__ float  Msh[HH];

    const int rb = blockIdx.x, s = blockIdx.y;
    const int i0 = rb * 64, j0 = s * 512;
    const int t = threadIdx.x;
    const int h = t >> 6, r = t & 63;
    const int i = i0 + r;
    const int warp = t >> 5, lane = t & 31;

    // per-head global max from partials
    if (t < HH) {
        float m = -1e30f;
        #pragma unroll
        for (int k = 0; k < 16; k++) m = fmaxf(m, g_pmax[t][k]);
        Msh[t] = m;
    }
    __syncthreads();
    const float M = Msh[h];
    const float u = g_ssrc[h][i] + M;
    const float c = fmaxf(u, ALPHA * u);
    const float P = __expf(u - c);
    const float Q = __expf(ALPHA * u - c);

    ull a0 = 0, a1 = 0, a2 = 0, a3 = 0;
    float den = 0.f;

    for (int jc = 0; jc < 512; jc += 128) {
        __syncthreads();
        // Wh chunk: 1024 float4
        #pragma unroll
        for (int it = 0; it < 4; it++) {
            int idx = t + it * 256;
            int rr = idx >> 3, c4 = (idx & 7) << 2;
            *(float4*)&Whs[rr * 32 + c4] = *(const float4*)&g_Wh[(j0 + jc + rr) * 32 + c4];
        }
        // exp factors: 512 (h,j) pairs, 2 per thread
        #pragma unroll
        for (int it = 0; it < 2; it++) {
            int idx = t + it * 256;
            int hh = idx >> 7, jj = idx & 127;
            float sd = g_sdst[hh][j0 + jc + jj];
            float MM = Msh[hh];
            pqs[hh][jj] = make_float2(__expf(sd - MM), __expf(ALPHA * (sd - MM)));
        }
        // adj bits: 256 words via ballot
        for (int wd = warp; wd < 256; wd += 8) {
            int rr = wd >> 2, jw = wd & 3;
            int v = adj[(size_t)(i0 + rr) * NN + j0 + jc + jw * 32 + lane];
            unsigned b = __ballot_sync(0xffffffffu, v > 0);
            if (lane == 0) ((unsigned*)&maskJ4[rr])[jw] = b;
        }
        __syncthreads();

        uint4 mw4 = maskJ4[r];
        unsigned mw[4] = {mw4.x, mw4.y, mw4.z, mw4.w};
        #pragma unroll
        for (int jw = 0; jw < 4; jw++) {
            unsigned word = mw[jw];
            #pragma unroll
            for (int jb = 0; jb < 32; jb++) {
                int jj = jw * 32 + jb;
                float2 pq = pqs[h][jj];
                // exp(lrelu(s)) = max(exp(s), exp(alpha*s)) since alpha < 1
                float w = fmaxf(P * pq.x, Q * pq.y);
                w = (word & (1u << jb)) ? w : 0.f;
                den += w;
                ull ww = pack2(w);
                ulonglong2 v01 = *(const ulonglong2*)&Whs[jj * 32 + h * 8];
                ulonglong2 v23 = *(const ulonglong2*)&Whs[jj * 32 + h * 8 + 4];
                a0 = fma2(ww, v01.x, a0);
                a1 = fma2(ww, v01.y, a1);
                a2 = fma2(ww, v23.x, a2);
                a3 = fma2(ww, v23.y, a3);
            }
        }
    }

    ull* dp = (ull*)&g_part[s][h][i][0];
    dp[0] = a0; dp[1] = a1; dp[2] = a2; dp[3] = a3;
    g_pden[s][h][i] = den;
}

// ---------------- K4: combine splits, mean heads, log_softmax, partial linear ----------------
__global__ void __launch_bounds__(256) k4_epilogue(const float* __restrict__ wlin,
                                                   float* __restrict__ dout) {
    __shared__ float rsm[8][8];
    const int t = threadIdx.x;
    const int i = blockIdx.x * 256 + t;
    const int warp = t >> 5, lane = t & 31;

    float embacc[8];
    #pragma unroll
    for (int o = 0; o < 8; o++) embacc[o] = 0.f;

    #pragma unroll
    for (int h = 0; h < HH; h++) {
        float dn = 0.f;
        float hv[8];
        #pragma unroll
        for (int o = 0; o < 8; o++) hv[o] = 0.f;
        #pragma unroll
        for (int s = 0; s < JSPLIT; s++) {
            dn += g_pden[s][h][i];
            float4 A = *(const float4*)&g_part[s][h][i][0];
            float4 B = *(const float4*)&g_part[s][h][i][4];
            hv[0] += A.x; hv[1] += A.y; hv[2] += A.z; hv[3] += A.w;
            hv[4] += B.x; hv[5] += B.y; hv[6] += B.z; hv[7] += B.w;
        }
        float inv = 1.0f / dn;
        #pragma unroll
        for (int o = 0; o < 8; o++) embacc[o] += hv[o] * inv;
    }

    float emb[8];
    #pragma unroll
    for (int o = 0; o < 8; o++) emb[o] = 0.25f * embacc[o];

    *(float4*)&dout[8 + i * 8]     = make_float4(emb[0], emb[1], emb[2], emb[3]);
    *(float4*)&dout[8 + i * 8 + 4] = make_float4(emb[4], emb[5], emb[6], emb[7]);

    float m = emb[0];
    #pragma unroll
    for (int o = 1; o < 8; o++) m = fmaxf(m, emb[o]);
    float sum = 0.f;
    #pragma unroll
    for (int o = 0; o < 8; o++) sum += expf(emb[o] - m);
    float lse = m + logf(sum);

    float wl = wlin[i];
    float cc[8];
    #pragma unroll
    for (int o = 0; o < 8; o++) cc[o] = (emb[o] - lse) * wl;

    #pragma unroll
    for (int off = 16; off; off >>= 1)
        #pragma unroll
        for (int o = 0; o < 8; o++)
            cc[o] += __shfl_xor_sync(0xffffffffu, cc[o], off);

    if (lane == 0) {
        #pragma unroll
        for (int o = 0; o < 8; o++) rsm[warp][o] = cc[o];
    }
    __syncthreads();
    if (t < 8) {
        float s2 = 0.f;
        #pragma unroll
        for (int w = 0; w < 8; w++) s2 += rsm[w][t];
        g_outpart[blockIdx.x][t] = s2;
    }
}

// ---------------- K5: final 8-element reduce ----------------
__global__ void k5_final(const float* __restrict__ blin, float* __restrict__ dout) {
    int t = threadIdx.x;
    if (t < 8) {
        float s = blin[0];
        #pragma unroll
        for (int b = 0; b < 16; b++) s += g_outpart[b][t];
        dout[t] = s;
    }
}

// ---------------- launch ----------------
extern "C" void kernel_launch(void* const* d_in, const int* in_sizes, int n_in,
                              void* d_out, int out_size) {
    const float* x    = (const float*)d_in[0];
    const int*   adj  = (const int*)d_in[1];
    const float* W    = (const float*)d_in[2];
    const float* a    = (const float*)d_in[3];
    const float* wlin = (const float*)d_in[4];
    const float* blin = (const float*)d_in[5];
    float* out = (float*)d_out;

    k0_repack<<<512, 256>>>(W);
    k1_gemm<<<dim3(32, KSPLIT), 128>>>(x);
    k2a_scores<<<16, 256>>>(a);
    k3_attn<<<dim3(64, 8), 256>>>(adj);
    k4_epilogue<<<16, 256>>>(wlin, out);
    k5_final<<<1, 32>>>(blin, out);
}

// round 4
// speedup vs baseline: 1.4299x; 1.4299x over previous
#include <cuda_runtime.h>

#define NN 4096
#define NF 4096
#define HH 4
#define OO 8
#define C32 32
#define ALPHA 0.2f
#define KSPLIT 8
#define JSPLIT 8

typedef unsigned long long ull;

// ---------------- device scratch ----------------
__device__ float  g_Wc[NF * C32];               // repacked W: [k][h*8+o]
__device__ float  g_Whp[KSPLIT][NN * C32];      // GEMM k-split partials
__device__ float  g_Wh[NN * C32];               // Wh: [node][h*8+o]
__device__ float  g_ssrc[HH][NN];
__device__ float  g_sdst[HH][NN];
__device__ float  g_pmax[HH][16];               // per-block partial max of s_dst
__device__ float  g_part[JSPLIT][HH][NN][OO];   // attention numerator partials
__device__ float  g_pden[JSPLIT][HH][NN];       // denominator partials
__device__ float  g_outpart[16][OO];            // final linear partials

__device__ __forceinline__ ull fma2(ull a, ull b, ull c) {
    ull d;
    asm("fma.rn.f32x2 %0, %1, %2, %3;" : "=l"(d) : "l"(a), "l"(b), "l"(c));
    return d;
}
__device__ __forceinline__ ull pack2(float v) {
    ull d; unsigned u = __float_as_uint(v);
    asm("mov.b64 %0, {%1, %1};" : "=l"(d) : "r"(u));
    return d;
}

// ---------------- K0: repack W [H][F][O] -> [F][H*O] ----------------
__global__ void k0_repack(const float* __restrict__ W) {
    int idx = blockIdx.x * 256 + threadIdx.x;
    if (idx < NF * C32) {
        int k = idx >> 5, c = idx & 31;
        int h = c >> 3, o = c & 7;
        g_Wc[idx] = W[(h * NF + k) * OO + o];
    }
}

// ---------------- K1: Wh = x @ Wc  (4 rows x 8 cols per thread) ----------------
// grid (32 rowblocks of 128 rows, KSPLIT), 128 threads
__global__ void __launch_bounds__(128) k1_gemm(const float* __restrict__ x) {
    __shared__ __align__(16) float xs[128 * 68];   // 34.8 KB row-major
    __shared__ __align__(16) float ws[64 * 32];    // 8 KB
    const int rb = blockIdx.x, ks = blockIdx.y;
    const int i0 = rb * 128, k0 = ks * 512;
    const int t = threadIdx.x;
    const int rg = t >> 2;           // 0..31, rows rg, rg+32, rg+64, rg+96
    const int cg = t & 3;            // 0..3, cols cg*8 .. cg*8+7

    ull acc[16];
    #pragma unroll
    for (int q = 0; q < 16; q++) acc[q] = 0;

    for (int kb = 0; kb < 512; kb += 64) {
        __syncthreads();
        // xs: 128 rows x 64 k = 2048 float4
        #pragma unroll
        for (int it = 0; it < 16; it++) {
            int idx = t + it * 128;
            int rr = idx >> 4, c4 = (idx & 15) << 2;
            *(float4*)&xs[rr * 68 + c4] =
                *(const float4*)&x[(size_t)(i0 + rr) * NF + k0 + kb + c4];
        }
        // ws: 64 k x 32 cols = 512 float4
        #pragma unroll
        for (int it = 0; it < 4; it++) {
            int idx = t + it * 128;
            int rr = idx >> 3, c4 = (idx & 7) << 2;
            *(float4*)&ws[rr * 32 + c4] = *(const float4*)&g_Wc[(k0 + kb + rr) * 32 + c4];
        }
        __syncthreads();
        #pragma unroll 4
        for (int kk = 0; kk < 64; kk++) {
            ulonglong2 wA = *(const ulonglong2*)&ws[kk * 32 + cg * 8];
            ulonglong2 wB = *(const ulonglong2*)&ws[kk * 32 + cg * 8 + 4];
            #pragma unroll
            for (int m = 0; m < 4; m++) {
                ull xx = pack2(xs[(rg + 32 * m) * 68 + kk]);
                acc[m * 4 + 0] = fma2(xx, wA.x, acc[m * 4 + 0]);
                acc[m * 4 + 1] = fma2(xx, wA.y, acc[m * 4 + 1]);
                acc[m * 4 + 2] = fma2(xx, wB.x, acc[m * 4 + 2]);
                acc[m * 4 + 3] = fma2(xx, wB.y, acc[m * 4 + 3]);
            }
        }
    }
    #pragma unroll
    for (int m = 0; m < 4; m++) {
        ull* dst = (ull*)&g_Whp[ks][(size_t)(i0 + rg + 32 * m) * 32 + cg * 8];
        dst[0] = acc[m * 4 + 0]; dst[1] = acc[m * 4 + 1];
        dst[2] = acc[m * 4 + 2]; dst[3] = acc[m * 4 + 3];
    }
}

// ---------------- K2a: reduce k-split partials, scores + partial maxes ----------------
__global__ void __launch_bounds__(256) k2a_scores(const float* __restrict__ a) {
    __shared__ float sa[64];
    __shared__ float mred[HH][8];
    int t = threadIdx.x;
    if (t < 64) sa[t] = a[t];
    __syncthreads();
    int i = blockIdx.x * 256 + t;
    const int lane = t & 31, warp = t >> 5;

    float wh[32];
    #pragma unroll
    for (int c4 = 0; c4 < 8; c4++) {
        float4 s = make_float4(0.f, 0.f, 0.f, 0.f);
        #pragma unroll
        for (int ks = 0; ks < KSPLIT; ks++) {
            float4 v = *(const float4*)&g_Whp[ks][i * 32 + c4 * 4];
            s.x += v.x; s.y += v.y; s.z += v.z; s.w += v.w;
        }
        *(float4*)&g_Wh[i * 32 + c4 * 4] = s;
        wh[c4 * 4 + 0] = s.x; wh[c4 * 4 + 1] = s.y;
        wh[c4 * 4 + 2] = s.z; wh[c4 * 4 + 3] = s.w;
    }
    float sdv[HH];
    #pragma unroll
    for (int h = 0; h < HH; h++) {
        float ss = 0.f, sd = 0.f;
        #pragma unroll
        for (int o = 0; o < OO; o++) {
            ss += wh[h * 8 + o] * sa[h * 16 + o];
            sd += wh[h * 8 + o] * sa[h * 16 + 8 + o];
        }
        g_ssrc[h][i] = ss;
        g_sdst[h][i] = sd;
        sdv[h] = sd;
    }
    // per-head block max of s_dst
    #pragma unroll
    for (int h = 0; h < HH; h++) {
        float m = sdv[h];
        #pragma unroll
        for (int o = 16; o; o >>= 1) m = fmaxf(m, __shfl_xor_sync(0xffffffffu, m, o));
        if (lane == 0) mred[h][warp] = m;
    }
    __syncthreads();
    if (t < HH) {
        float m = -1e30f;
        #pragma unroll
        for (int w = 0; w < 8; w++) m = fmaxf(m, mred[t][w]);
        g_pmax[t][blockIdx.x] = m;
    }
}

// ---------------- K3: attention aggregation (hot kernel, factors fused) ----------------
// grid (64 rowblocks, 8 j-splits), 256 threads = 4 heads x 64 rows
__global__ void __launch_bounds__(256) k3_attn(const int* __restrict__ adj) {
    __shared__ __align__(16) float Whs[128 * 32];   // 16 KB
    __shared__ float2 pqs[HH][128];                 // 4 KB (p, q) per (head, j)
    __shared__ uint4  maskJ4[64];                   // 1 KB
    __shared__ float  Msh[HH];

    const int rb = blockIdx.x, s = blockIdx.y;
    const int i0 = rb * 64, j0 = s * 512;
    const int t = threadIdx.x;
    const int h = t >> 6, r = t & 63;
    const int i = i0 + r;
    const int warp = t >> 5, lane = t & 31;

    // per-head global max from partials
    if (t < HH) {
        float m = -1e30f;
        #pragma unroll
        for (int k = 0; k < 16; k++) m = fmaxf(m, g_pmax[t][k]);
        Msh[t] = m;
    }
    __syncthreads();
    const float M = Msh[h];
    const float u = g_ssrc[h][i] + M;
    const float c = fmaxf(u, ALPHA * u);
    const float P = __expf(u - c);
    const float Q = __expf(ALPHA * u - c);

    ull a0 = 0, a1 = 0, a2 = 0, a3 = 0;
    float den = 0.f;

    for (int jc = 0; jc < 512; jc += 128) {
        __syncthreads();
        // Wh chunk: 1024 float4
        #pragma unroll
        for (int it = 0; it < 4; it++) {
            int idx = t + it * 256;
            int rr = idx >> 3, c4 = (idx & 7) << 2;
            *(float4*)&Whs[rr * 32 + c4] = *(const float4*)&g_Wh[(j0 + jc + rr) * 32 + c4];
        }
        // exp factors: 512 (h,j) pairs, 2 per thread
        #pragma unroll
        for (int it = 0; it < 2; it++) {
            int idx = t + it * 256;
            int hh = idx >> 7, jj = idx & 127;
            float sd = g_sdst[hh][j0 + jc + jj];
            float MM = Msh[hh];
            pqs[hh][jj] = make_float2(__expf(sd - MM), __expf(ALPHA * (sd - MM)));
        }
        // adj bits: 256 words via ballot
        for (int wd = warp; wd < 256; wd += 8) {
            int rr = wd >> 2, jw = wd & 3;
            int v = adj[(size_t)(i0 + rr) * NN + j0 + jc + jw * 32 + lane];
            unsigned b = __ballot_sync(0xffffffffu, v > 0);
            if (lane == 0) ((unsigned*)&maskJ4[rr])[jw] = b;
        }
        __syncthreads();

        uint4 mw4 = maskJ4[r];
        unsigned mw[4] = {mw4.x, mw4.y, mw4.z, mw4.w};
        #pragma unroll
        for (int jw = 0; jw < 4; jw++) {
            unsigned word = mw[jw];
            #pragma unroll
            for (int jb = 0; jb < 32; jb++) {
                int jj = jw * 32 + jb;
                float2 pq = pqs[h][jj];
                // exp(lrelu(s)) = max(exp(s), exp(alpha*s)) since alpha < 1
                float w = fmaxf(P * pq.x, Q * pq.y);
                w = (word & (1u << jb)) ? w : 0.f;
                den += w;
                ull ww = pack2(w);
                ulonglong2 v01 = *(const ulonglong2*)&Whs[jj * 32 + h * 8];
                ulonglong2 v23 = *(const ulonglong2*)&Whs[jj * 32 + h * 8 + 4];
                a0 = fma2(ww, v01.x, a0);
                a1 = fma2(ww, v01.y, a1);
                a2 = fma2(ww, v23.x, a2);
                a3 = fma2(ww, v23.y, a3);
            }
        }
    }

    ull* dp = (ull*)&g_part[s][h][i][0];
    dp[0] = a0; dp[1] = a1; dp[2] = a2; dp[3] = a3;
    g_pden[s][h][i] = den;
}

// ---------------- K4: combine splits, mean heads, log_softmax, partial linear ----------------
__global__ void __launch_bounds__(256) k4_epilogue(const float* __restrict__ wlin,
                                                   float* __restrict__ dout) {
    __shared__ float rsm[8][8];
    const int t = threadIdx.x;
    const int i = blockIdx.x * 256 + t;
    const int warp = t >> 5, lane = t & 31;

    float embacc[8];
    #pragma unroll
    for (int o = 0; o < 8; o++) embacc[o] = 0.f;

    #pragma unroll
    for (int h = 0; h < HH; h++) {
        float dn = 0.f;
        float hv[8];
        #pragma unroll
        for (int o = 0; o < 8; o++) hv[o] = 0.f;
        #pragma unroll
        for (int s = 0; s < JSPLIT; s++) {
            dn += g_pden[s][h][i];
            float4 A = *(const float4*)&g_part[s][h][i][0];
            float4 B = *(const float4*)&g_part[s][h][i][4];
            hv[0] += A.x; hv[1] += A.y; hv[2] += A.z; hv[3] += A.w;
            hv[4] += B.x; hv[5] += B.y; hv[6] += B.z; hv[7] += B.w;
        }
        float inv = 1.0f / dn;
        #pragma unroll
        for (int o = 0; o < 8; o++) embacc[o] += hv[o] * inv;
    }

    float emb[8];
    #pragma unroll
    for (int o = 0; o < 8; o++) emb[o] = 0.25f * embacc[o];

    *(float4*)&dout[8 + i * 8]     = make_float4(emb[0], emb[1], emb[2], emb[3]);
    *(float4*)&dout[8 + i * 8 + 4] = make_float4(emb[4], emb[5], emb[6], emb[7]);

    float m = emb[0];
    #pragma unroll
    for (int o = 1; o < 8; o++) m = fmaxf(m, emb[o]);
    float sum = 0.f;
    #pragma unroll
    for (int o = 0; o < 8; o++) sum += expf(emb[o] - m);
    float lse = m + logf(sum);

    float wl = wlin[i];
    float cc[8];
    #pragma unroll
    for (int o = 0; o < 8; o++) cc[o] = (emb[o] - lse) * wl;

    #pragma unroll
    for (int off = 16; off; off >>= 1)
        #pragma unroll
        for (int o = 0; o < 8; o++)
            cc[o] += __shfl_xor_sync(0xffffffffu, cc[o], off);

    if (lane == 0) {
        #pragma unroll
        for (int o = 0; o < 8; o++) rsm[warp][o] = cc[o];
    }
    __syncthreads();
    if (t < 8) {
        float s2 = 0.f;
        #pragma unroll
        for (int w = 0; w < 8; w++) s2 += rsm[w][t];
        g_outpart[blockIdx.x][t] = s2;
    }
}

// ---------------- K5: final 8-element reduce ----------------
__global__ void k5_final(const float* __restrict__ blin, float* __restrict__ dout) {
    int t = threadIdx.x;
    if (t < 8) {
        float s = blin[0];
        #pragma unroll
        for (int b = 0; b < 16; b++) s += g_outpart[b][t];
        dout[t] = s;
    }
}

// ---------------- launch ----------------
extern "C" void kernel_launch(void* const* d_in, const int* in_sizes, int n_in,
                              void* d_out, int out_size) {
    const float* x    = (const float*)d_in[0];
    const int*   adj  = (const int*)d_in[1];
    const float* W    = (const float*)d_in[2];
    const float* a    = (const float*)d_in[3];
    const float* wlin = (const float*)d_in[4];
    const float* blin = (const float*)d_in[5];
    float* out = (float*)d_out;

    k0_repack<<<512, 256>>>(W);
    k1_gemm<<<dim3(32, KSPLIT), 128>>>(x);
    k2a_scores<<<16, 256>>>(a);
    k3_attn<<<dim3(64, 8), 256>>>(adj);
    k4_epilogue<<<16, 256>>>(wlin, out);
    k5_final<<<1, 32>>>(blin, out);
}